// round 2
// baseline (speedup 1.0000x reference)
#include <cuda_runtime.h>
#include <cuda_bf16.h>
#include <math.h>

// SwitchMoE with the reference's dim-1 scatter gate bug:
//   mask[b, top1[b,n], 0] = 1  =>  output nonzero only for n<8, expert 0.
// E=8, DIM=128, HID=512, OUT=128, B=16, H=W=64, N=4096.

#define BATCH 16
#define NTOK  4096
#define DIM   128
#define NEXP  8
#define HID   512
#define OUTD  128
#define EPS   1e-6f

// ---- scratch (device globals; no allocation allowed) ----
__device__ int   g_mask[BATCH * NEXP];            // mask[b][j] = 1 iff exists n with argmax==j
__device__ float g_prob0[BATCH * NEXP];           // softmax prob of expert 0 at token j<8
__device__ float g_h1[BATCH * 2 * 9 * HID];       // expert-0 fc1 at (h in {0,1}, w in [0,9))

// ------------------------------------------------------------------
// K0: zero the tiny scratch
// ------------------------------------------------------------------
__global__ void init_kernel() {
    int i = threadIdx.x;
    if (i < BATCH * NEXP) { g_mask[i] = 0; g_prob0[i] = 0.0f; }
}

// ------------------------------------------------------------------
// K1: gate logits -> argmax mask (+softmax p0 at n<8), fused with out-zeroing.
// 512 blocks x 128 threads, 128 tokens/block (1 token per thread).
// x staged through smem in 16-dim chunks so x loads are coalesced while each
// thread accumulates its own token's 8 logits from broadcast wg reads.
// ------------------------------------------------------------------
__global__ void __launch_bounds__(128) gate_kernel(
    const float* __restrict__ x, const float* __restrict__ wg,
    const float* __restrict__ bg, float* __restrict__ out)
{
    __shared__ float wg_s[DIM * NEXP];   // 1024
    __shared__ float bg_s[NEXP];
    __shared__ float xs[128 * 20];       // 128 tokens x 16 dims, row stride 20 (16B aligned, conflict-free)

    const int tid  = threadIdx.x;
    const int tok0 = blockIdx.x * 128;

    for (int i = tid; i < DIM * NEXP; i += 128) wg_s[i] = wg[i];
    if (tid < NEXP) bg_s[tid] = bg[tid];

    float acc[NEXP];
#pragma unroll
    for (int e = 0; e < NEXP; e++) acc[e] = 0.0f;

    for (int ch = 0; ch < 8; ch++) {        // 8 chunks x 16 dims = 128 dims
        __syncthreads();                     // protects xs reuse + first-iter wg_s visibility
        // stage 128 tokens x 16 dims (512 float4 loads, coalesced 64B/token)
#pragma unroll
        for (int k = 0; k < 4; k++) {
            int j = k * 128 + tid;
            int t = j >> 2, q = j & 3;
            float4 v = *(const float4*)(x + (size_t)(tok0 + t) * DIM + ch * 16 + q * 4);
            *(float4*)(xs + t * 20 + q * 4) = v;
        }
        __syncthreads();
#pragma unroll
        for (int d4 = 0; d4 < 4; d4++) {
            float4 xv = *(const float4*)(xs + tid * 20 + d4 * 4);
            float xarr[4] = {xv.x, xv.y, xv.z, xv.w};
#pragma unroll
            for (int jj = 0; jj < 4; jj++) {
                int dd = ch * 16 + d4 * 4 + jj;
                float4 w0 = *(const float4*)(wg_s + dd * 8);
                float4 w1 = *(const float4*)(wg_s + dd * 8 + 4);
                float xd = xarr[jj];
                acc[0] += xd * w0.x; acc[1] += xd * w0.y;
                acc[2] += xd * w0.z; acc[3] += xd * w0.w;
                acc[4] += xd * w1.x; acc[5] += xd * w1.y;
                acc[6] += xd * w1.z; acc[7] += xd * w1.w;
            }
        }
    }

    // finalize: argmax (first-max, matching jnp.argmax), mask store, softmax p0 at n<8
    float l[NEXP];
#pragma unroll
    for (int e = 0; e < NEXP; e++) l[e] = acc[e] + bg_s[e];
    float m = l[0]; int am = 0;
#pragma unroll
    for (int e = 1; e < NEXP; e++) if (l[e] > m) { m = l[e]; am = e; }

    const int tok = tok0 + tid;
    const int b = tok >> 12;
    const int n = tok & (NTOK - 1);
    g_mask[b * NEXP + am] = 1;            // benign write-write race: same value
    if (n < NEXP) {
        float s = 0.0f;
#pragma unroll
        for (int e = 0; e < NEXP; e++) s += expf(l[e] - m);
        g_prob0[b * NEXP + n] = expf(l[0] - m) / s;
    }

    // zero this block's 128 output rows (contiguous 64KB)
    float4 z = make_float4(0.f, 0.f, 0.f, 0.f);
    float* ob = out + (size_t)tok0 * OUTD;
#pragma unroll 8
    for (int i = tid; i < 128 * (OUTD / 4); i += 128)
        *(float4*)(ob + (size_t)i * 4) = z;
}

// ------------------------------------------------------------------
// K2: expert-0 fc1 at the 18 needed pixels per batch (h in {0,1}, w in [0,9)).
// grid (16 batches, 8 channel-groups of 64), 128 threads.
// thread -> (channel c, token parity t0), 9 tokens each, W1 loads coalesced.
// ------------------------------------------------------------------
__global__ void __launch_bounds__(128) fc1_kernel(
    const float* __restrict__ x, const float* __restrict__ W1,
    const float* __restrict__ B1)
{
    __shared__ float xs[18 * DIM];
    const int b = blockIdx.x, cg = blockIdx.y;
    const int tid = threadIdx.x;

    for (int i = tid; i < 18 * DIM; i += 128) {
        int p = i >> 7, d = i & (DIM - 1);
        int h = p / 9, w = p % 9;
        int nn = h * 64 + w;
        xs[p * DIM + d] = x[((size_t)b * NTOK + nn) * DIM + d];
    }
    __syncthreads();

    const int c  = cg * 64 + (tid & 63);
    const int t0 = tid >> 6;              // 0 or 1 -> tokens t0, t0+2, ..., t0+16

    float acc[9];
    float bv = B1[c];
#pragma unroll
    for (int k = 0; k < 9; k++) acc[k] = bv;

    for (int d4 = 0; d4 < DIM / 4; d4++) {
        float4 xv[9];
#pragma unroll
        for (int k = 0; k < 9; k++)
            xv[k] = *(const float4*)(xs + (t0 + 2 * k) * DIM + d4 * 4);
#pragma unroll
        for (int j = 0; j < 4; j++) {
            float w = W1[(size_t)(d4 * 4 + j) * HID + c];
            acc[0] += xv[0].x * 0.0f; // placeholder removed below
            // (unrolled via array view)
            float* xf0 = (float*)&xv[0];
            (void)xf0;
#pragma unroll
            for (int k = 0; k < 9; k++) {
                float xd = ((const float*)&xv[k])[j];
                acc[k] += xd * w;
            }
        }
    }

#pragma unroll
    for (int k = 0; k < 9; k++) {
        int p = t0 + 2 * k;
        int h = p / 9, w = p % 9;
        g_h1[(((size_t)b * 2 + h) * 9 + w) * HID + c] = acc[k];
    }
}

// ------------------------------------------------------------------
// K3: dwconv(3x3, SAME) + bias + exact GELU + fc2 + gate scaling, for the
// 128 nonzero output rows (b in [0,16), j in [0,8)). grid (16, 8) x 128 thr.
// ------------------------------------------------------------------
__global__ void __launch_bounds__(128) out_kernel(
    const float* __restrict__ Wd, const float* __restrict__ Bd,
    const float* __restrict__ W2, const float* __restrict__ B2,
    float* __restrict__ out)
{
    const int b = blockIdx.x, j = blockIdx.y;
    const int tid = threadIdx.x;
    __shared__ float gs[HID];
    __shared__ float gate_s;

    if (tid == 0) {
        float s = 0.0f;
#pragma unroll
        for (int bb = 0; bb < BATCH; bb++)
            s += g_prob0[bb * NEXP + j] * (float)g_mask[bb * NEXP + j];
        float gv = g_prob0[b * NEXP + j] * (float)g_mask[b * NEXP + j];
        gate_s = gv / (s + EPS) * (float)BATCH;   // capacity = 16.0
    }

    // depthwise conv at (h=0, w=j): kh in {1,2} -> h' in {0,1}; w' = j+kw-1
#pragma unroll
    for (int k = 0; k < HID / 128; k++) {
        int c = tid + k * 128;
        float conv = Bd[c];
#pragma unroll
        for (int hh = 0; hh < 2; hh++) {
#pragma unroll
            for (int kw = 0; kw < 3; kw++) {
                int wp = j + kw - 1;
                if (wp >= 0 && wp <= 8) {
                    conv += g_h1[(((size_t)b * 2 + hh) * 9 + wp) * HID + c]
                          * Wd[((hh + 1) * 3 + kw) * HID + c];
                }
            }
        }
        // exact GELU: 0.5*x*(1+erf(x/sqrt(2)))
        gs[c] = 0.5f * conv * (1.0f + erff(conv * 0.70710678118654752f));
    }
    __syncthreads();

    float acc = B2[tid];
#pragma unroll 8
    for (int c = 0; c < HID; c++)
        acc += gs[c] * W2[(size_t)c * OUTD + tid];

    out[(((size_t)b * NTOK + j) * OUTD) + tid] = gate_s * acc;
}

// ------------------------------------------------------------------
extern "C" void kernel_launch(void* const* d_in, const int* in_sizes, int n_in,
                              void* d_out, int out_size)
{
    // input order: x, [H, W,] wg, bg, W1, B1, Wd, Bd, W2, B2
    int o = (n_in >= 11) ? 3 : 1;   // skip H, W scalars if present
    const float* x  = (const float*)d_in[0];
    const float* wg = (const float*)d_in[o + 0];
    const float* bg = (const float*)d_in[o + 1];
    const float* W1 = (const float*)d_in[o + 2];
    const float* B1 = (const float*)d_in[o + 3];
    const float* Wd = (const float*)d_in[o + 4];
    const float* Bd = (const float*)d_in[o + 5];
    const float* W2 = (const float*)d_in[o + 6];
    const float* B2 = (const float*)d_in[o + 7];
    float* out = (float*)d_out;

    init_kernel<<<1, 128>>>();
    gate_kernel<<<512, 128>>>(x, wg, bg, out);
    fc1_kernel<<<dim3(16, 8), 128>>>(x, W1, B1);
    out_kernel<<<dim3(16, 8), 128>>>(Wd, Bd, W2, B2, out);
}

// round 5
// speedup vs baseline: 2.0732x; 2.0732x over previous
#include <cuda_runtime.h>
#include <cuda_bf16.h>
#include <math.h>

// SwitchMoE with the reference's dim-1 scatter gate bug:
//   mask[b, top1[b,n], 0] = 1  =>  output nonzero only for n<8, expert 0.
// E=8, DIM=128, HID=512, OUT=128, B=16, H=W=64, N=4096.
//
// 2 launches:
//   K1 (grid 640): blocks <512 = gate logits/argmax + out zeroing (+ per-block
//                  argmax bitmask, replay-safe, no init needed);
//                  blocks >=512 = expert-0 fc1 at the 18 needed pixels/batch.
//   K2 (grid 16x8, 512 thr): dwconv+GELU+fc2+gate for the 128 nonzero rows.

#define BATCH 16
#define NTOK  4096
#define DIM   128
#define NEXP  8
#define HID   512
#define OUTD  128
#define EPS   1e-6f

// ---- scratch (device globals; every element rewritten each call) ----
__device__ unsigned g_bm[512];                    // per-gate-block OR of (1<<argmax)
__device__ float    g_prob0[BATCH * NEXP];        // softmax p(expert0) at token n<8
__device__ float    g_h1[BATCH * 2 * 9 * HID];    // expert-0 fc1 at (h in {0,1}, w in [0,9))

// ------------------------------------------------------------------
// K1: fused gate (+zero out) and fc1
// ------------------------------------------------------------------
__global__ void __launch_bounds__(128) gate_fc1_kernel(
    const float* __restrict__ x, const float* __restrict__ wg,
    const float* __restrict__ bg, const float* __restrict__ W1,
    const float* __restrict__ B1, float* __restrict__ out)
{
    // shared pool, aliased per path:
    //   gate: wg_s[1024] | bg_s[8] | xs[128*20]   = 3592 floats
    //   fc1 : xs18[18*128]                        = 2304 floats
    __shared__ float pool[3592];
    __shared__ unsigned warpor[4];

    const int tid = threadIdx.x;

    if (blockIdx.x < 512) {
        // ================= gate path =================
        float* wg_s = pool;                // [DIM*NEXP]
        float* bg_s = pool + 1024;         // [NEXP]
        float* xs   = pool + 1032;         // [128*20] row stride 20 -> conflict-free

        const int tok0 = blockIdx.x * 128;

        for (int i = tid; i < DIM * NEXP; i += 128) wg_s[i] = wg[i];
        if (tid < NEXP) bg_s[tid] = bg[tid];

        float acc[NEXP];
#pragma unroll
        for (int e = 0; e < NEXP; e++) acc[e] = 0.0f;

        for (int ch = 0; ch < 8; ch++) {       // 8 chunks x 16 dims
            __syncthreads();                    // xs reuse + first-iter wg_s visibility
#pragma unroll
            for (int k = 0; k < 4; k++) {
                int j = k * 128 + tid;
                int t = j >> 2, q = j & 3;
                float4 v = *(const float4*)(x + (size_t)(tok0 + t) * DIM + ch * 16 + q * 4);
                *(float4*)(xs + t * 20 + q * 4) = v;
            }
            __syncthreads();
#pragma unroll
            for (int d4 = 0; d4 < 4; d4++) {
                float4 xv = *(const float4*)(xs + tid * 20 + d4 * 4);
                float xarr[4] = {xv.x, xv.y, xv.z, xv.w};
#pragma unroll
                for (int jj = 0; jj < 4; jj++) {
                    int dd = ch * 16 + d4 * 4 + jj;
                    float4 w0 = *(const float4*)(wg_s + dd * 8);
                    float4 w1 = *(const float4*)(wg_s + dd * 8 + 4);
                    float xd = xarr[jj];
                    acc[0] += xd * w0.x; acc[1] += xd * w0.y;
                    acc[2] += xd * w0.z; acc[3] += xd * w0.w;
                    acc[4] += xd * w1.x; acc[5] += xd * w1.y;
                    acc[6] += xd * w1.z; acc[7] += xd * w1.w;
                }
            }
        }

        // finalize: logits, first-max argmax (matches jnp.argmax), softmax p0
        float l[NEXP];
#pragma unroll
        for (int e = 0; e < NEXP; e++) l[e] = acc[e] + bg_s[e];
        float m = l[0]; int am = 0;
#pragma unroll
        for (int e = 1; e < NEXP; e++) if (l[e] > m) { m = l[e]; am = e; }

        const int tok = tok0 + tid;
        const int b = tok >> 12;
        const int n = tok & (NTOK - 1);
        if (n < NEXP) {
            float s = 0.0f;
#pragma unroll
            for (int e = 0; e < NEXP; e++) s += expf(l[e] - m);
            g_prob0[b * NEXP + n] = expf(l[0] - m) / s;
        }

        // per-block argmax bitmask (replay-safe: every slot rewritten each call)
        unsigned wor = __reduce_or_sync(0xffffffffu, 1u << am);
        if ((tid & 31) == 0) warpor[tid >> 5] = wor;

        // zero this block's 128 output rows (contiguous 64KB)
        float4 z = make_float4(0.f, 0.f, 0.f, 0.f);
        float* ob = out + (size_t)tok0 * OUTD;
#pragma unroll 8
        for (int i = tid; i < 128 * (OUTD / 4); i += 128)
            *(float4*)(ob + (size_t)i * 4) = z;

        __syncthreads();
        if (tid == 0)
            g_bm[blockIdx.x] = warpor[0] | warpor[1] | warpor[2] | warpor[3];
    } else {
        // ================= fc1 path =================
        // expert-0 fc1 at 18 pixels/batch: h in {0,1}, w in [0,9)
        float* xs = pool;                  // [18*DIM]
        const int bb = blockIdx.x - 512;   // [0,128)
        const int b  = bb >> 3, cg = bb & 7;

        for (int i = tid; i < 18 * DIM; i += 128) {
            int p = i >> 7, d = i & (DIM - 1);
            int h = p / 9, w = p % 9;
            int nn = h * 64 + w;
            xs[p * DIM + d] = x[((size_t)b * NTOK + nn) * DIM + d];
        }
        __syncthreads();

        const int c  = cg * 64 + (tid & 63);
        const int t0 = tid >> 6;           // tokens t0, t0+2, ..., t0+16

        float acc9[9];
        float bv = B1[c];
#pragma unroll
        for (int k = 0; k < 9; k++) acc9[k] = bv;

        for (int d4 = 0; d4 < DIM / 4; d4++) {
            float4 xv[9];
#pragma unroll
            for (int k = 0; k < 9; k++)
                xv[k] = *(const float4*)(xs + (t0 + 2 * k) * DIM + d4 * 4);
#pragma unroll
            for (int j = 0; j < 4; j++) {
                float w = W1[(size_t)(d4 * 4 + j) * HID + c];
#pragma unroll
                for (int k = 0; k < 9; k++) {
                    float xd = ((const float*)&xv[k])[j];
                    acc9[k] += xd * w;
                }
            }
        }

#pragma unroll
        for (int k = 0; k < 9; k++) {
            int p = t0 + 2 * k;
            int h = p / 9, w = p % 9;
            g_h1[(((size_t)b * 2 + h) * 9 + w) * HID + c] = acc9[k];
        }
    }
}

// ------------------------------------------------------------------
// K2: dwconv(3x3, SAME) + bias + exact GELU + fc2 + gate, 128 nonzero rows.
// grid (16,8) x 512 threads. conv: 1 channel/thread. fc2: HID split 4-way.
// ------------------------------------------------------------------
__global__ void __launch_bounds__(512) out_kernel(
    const float* __restrict__ Wd, const float* __restrict__ Bd,
    const float* __restrict__ W2, const float* __restrict__ B2,
    float* __restrict__ out)
{
    const int b = blockIdx.x, j = blockIdx.y;
    const int tid = threadIdx.x;
    __shared__ float gs[HID];
    __shared__ float partial[512];
    __shared__ float maskv[BATCH];
    __shared__ float gate_s;

    // mask[b', j] = OR over the 32 gate blocks of batch b' of bit j.
    // tid = b'*32 + blk exactly (512 threads, 512 gate blocks).
    {
        unsigned bit = (g_bm[tid] >> j) & 1u;
        unsigned m = __reduce_or_sync(0xffffffffu, bit);
        if ((tid & 31) == 0) maskv[tid >> 5] = (float)m;
    }

    // depthwise conv at (h=0, w=j): kh in {1,2} -> h' in {0,1}; w' = j+kw-1
    {
        const int c = tid;                 // HID == 512 == blockDim
        float conv = Bd[c];
#pragma unroll
        for (int hh = 0; hh < 2; hh++) {
#pragma unroll
            for (int kw = 0; kw < 3; kw++) {
                int wp = j + kw - 1;
                if (wp >= 0 && wp <= 8) {
                    conv += g_h1[(((size_t)b * 2 + hh) * 9 + wp) * HID + c]
                          * Wd[((hh + 1) * 3 + kw) * HID + c];
                }
            }
        }
        // exact GELU: 0.5*x*(1+erf(x/sqrt(2)))
        gs[c] = 0.5f * conv * (1.0f + erff(conv * 0.70710678118654752f));
    }
    __syncthreads();

    if (tid == 0) {
        float s = 0.0f;
#pragma unroll
        for (int bb = 0; bb < BATCH; bb++)
            s += g_prob0[bb * NEXP + j] * maskv[bb];
        float gv = g_prob0[b * NEXP + j] * maskv[b];
        gate_s = gv / (s + EPS) * (float)BATCH;   // capacity = 16.0
    }

    // fc2: thread (s,o) sums c in [s*128,(s+1)*128)
    {
        const int s = tid >> 7, o = tid & (OUTD - 1);
        const float* w2p = W2 + (size_t)(s * 128) * OUTD + o;
        const float* gp  = gs + s * 128;
        float acc = 0.0f;
#pragma unroll 16
        for (int c = 0; c < 128; c++)
            acc += gp[c] * w2p[(size_t)c * OUTD];
        partial[tid] = acc;
    }
    __syncthreads();

    if (tid < OUTD) {
        float r = partial[tid] + partial[128 + tid] + partial[256 + tid]
                + partial[384 + tid] + B2[tid];
        out[((size_t)b * NTOK + j) * OUTD + tid] = gate_s * r;
    }
}

// ------------------------------------------------------------------
extern "C" void kernel_launch(void* const* d_in, const int* in_sizes, int n_in,
                              void* d_out, int out_size)
{
    // input order: x, [H, W,] wg, bg, W1, B1, Wd, Bd, W2, B2
    int o = (n_in >= 11) ? 3 : 1;
    const float* x  = (const float*)d_in[0];
    const float* wg = (const float*)d_in[o + 0];
    const float* bg = (const float*)d_in[o + 1];
    const float* W1 = (const float*)d_in[o + 2];
    const float* B1 = (const float*)d_in[o + 3];
    const float* Wd = (const float*)d_in[o + 4];
    const float* Bd = (const float*)d_in[o + 5];
    const float* W2 = (const float*)d_in[o + 6];
    const float* B2 = (const float*)d_in[o + 7];
    float* out = (float*)d_out;

    gate_fc1_kernel<<<640, 128>>>(x, wg, bg, W1, B1, out);
    out_kernel<<<dim3(16, 8), 512>>>(Wd, Bd, W2, B2, out);
}